// round 5
// baseline (speedup 1.0000x reference)
#include <cuda_runtime.h>
#include <cstdint>
#include <math.h>

// ---------------------------------------------------------------------------
// Problem constants
// ---------------------------------------------------------------------------
#define BATCH   8
#define SEQL    2048
#define D_IN    512
#define DMODEL  1024
#define NROW    (BATCH * SEQL)          // 16384
#define LN_EPS  1e-5f

typedef unsigned short u16;
typedef uint32_t u32;

// element counts
static const long long C_IN  = (long long)NROW * D_IN;       // 8388608
static const long long C_EW  = (long long)DMODEL * D_IN;     // 524288
static const long long C_W   = (long long)DMODEL * DMODEL;   // 1048576
static const long long C_MAT = (long long)NROW * DMODEL;     // 16777216
static const long long C_SC  = (long long)BATCH * SEQL * SEQL; // 33554432

// scratch offsets (in floats; a split hi+lo pair of N elems occupies N floats)
#define O_INS   (0LL)
#define O_EWS   (O_INS  + C_IN)
#define O_WQS   (O_EWS  + C_EW)
#define O_WKS   (O_WQS  + C_W)
#define O_WVS   (O_WKS  + C_W)
#define O_SKWS  (O_WVS  + C_W)
#define O_X     (O_SKWS + C_W)
#define O_XS    (O_X    + C_MAT)
#define O_QS    (O_XS   + C_MAT)
#define O_KS    (O_QS   + C_MAT)
#define O_VTS   (O_KS   + C_MAT)
#define O_SC    (O_VTS  + C_MAT)
#define O_SCS   (O_SC   + C_SC)
#define O_Z     (O_SCS  + C_SC)
#define O_H     (O_Z    + C_MAT)
#define O_HS    (O_H    + C_MAT)
#define O_SK    (O_HS   + C_MAT)
#define O_T     (O_SK   + C_MAT)
#define O_TOTAL (O_T    + 16384)

__device__ float g_scratch[O_TOTAL];

// ---------------------------------------------------------------------------
// PTX helpers (baseline sm_80+ features only — harness targets plain sm_103)
// ---------------------------------------------------------------------------
__device__ __forceinline__ u32 smem_u32(const void* p) {
    u32 a;
    asm("{ .reg .u64 t; cvta.to.shared.u64 t, %1; cvt.u32.u64 %0, t; }"
        : "=r"(a) : "l"(p));
    return a;
}

__device__ __forceinline__ void cp_async16(u32 dst, const void* src) {
    asm volatile("cp.async.cg.shared.global [%0], [%1], 16;" :: "r"(dst), "l"(src));
}
#define CP_COMMIT() asm volatile("cp.async.commit_group;" ::: "memory")
#define CP_WAIT1()  asm volatile("cp.async.wait_group 1;"  ::: "memory")

// split x0,x1 (fp32) into packed bf16x2 hi and lo parts: x = hi + lo
__device__ __forceinline__ void split_pack(float x0, float x1, u32& hi, u32& lo) {
    asm("cvt.rn.bf16x2.f32 %0, %1, %2;" : "=r"(hi) : "f"(x1), "f"(x0));
    const float h0 = __uint_as_float(hi << 16);
    const float h1 = __uint_as_float(hi & 0xFFFF0000u);
    const float l0 = x0 - h0;
    const float l1 = x1 - h1;
    asm("cvt.rn.bf16x2.f32 %0, %1, %2;" : "=r"(lo) : "f"(l1), "f"(l0));
}

// D += A*B  (m16n8k16 bf16, fp32 accum)
__device__ __forceinline__ void mma_bf16(float* d, const u32* a, const u32* b) {
    asm volatile(
        "mma.sync.aligned.m16n8k16.row.col.f32.bf16.bf16.f32 "
        "{%0,%1,%2,%3}, {%4,%5,%6,%7}, {%8,%9}, {%0,%1,%2,%3};"
        : "+f"(d[0]), "+f"(d[1]), "+f"(d[2]), "+f"(d[3])
        : "r"(a[0]), "r"(a[1]), "r"(a[2]), "r"(a[3]), "r"(b[0]), "r"(b[1]));
}

__device__ __forceinline__ void ldmat4(u32& r0, u32& r1, u32& r2, u32& r3, u32 addr) {
    asm volatile("ldmatrix.sync.aligned.m8n8.x4.shared.b16 {%0,%1,%2,%3}, [%4];"
                 : "=r"(r0), "=r"(r1), "=r"(r2), "=r"(r3) : "r"(addr));
}

// ---------------------------------------------------------------------------
// bf16x3 split GEMM on pre-split hi/lo planes:
//   C[m,n] = alpha * sum_k A[m,k]*B[n,k]  (+bias +posenc)
// A planes [M][K] bf16, B planes [N][K] bf16. Tile 128x128x32, 256 thr,
// 8 warps (2x4), warp tile 64x32. ldmatrix fragments, 2-stage cp.async.
//   F32OUT:  write fp32 C
//   SPLITOUT: write bf16 hi/lo planes of C
//   TRANSOUT: (V only) split planes written transposed per batch:
//             out[b][n][s] with m = b*SEQL + s
// ---------------------------------------------------------------------------
#define TROW_B   80                     // bytes per smem tile row (64 data + 16 pad)
#define PLANE_B  (128 * TROW_B)         // 10240
#define STAGE_B  (4 * PLANE_B)          // 40960
#define DYN_SMEM_G (2 * STAGE_B)        // 81920

template <bool F32OUT, bool SPLITOUT, bool TRANSOUT>
__global__ __launch_bounds__(256, 2)
void tc_gemm(const u16* __restrict__ Ahi, const u16* __restrict__ Alo,
             const u16* __restrict__ Bhi, const u16* __restrict__ Blo,
             float* __restrict__ Cf, u16* __restrict__ Chi, u16* __restrict__ Clo,
             int M, int N, int K,
             long long sA, long long sB, long long sC,
             float alpha, const float* __restrict__ bias,
             const float* __restrict__ posenc)
{
    extern __shared__ char smem[];

    const int tid  = threadIdx.x;
    const int wid  = tid >> 5;
    const int lane = tid & 31;
    const int wm   = wid >> 2;       // 0..1 (M)
    const int wn   = wid & 3;        // 0..3 (N)
    const int g    = lane >> 2;      // groupID 0..7
    const int t    = lane & 3;       // threadID_in_group
    const int lrow = lane & 15;
    const int lch  = lane >> 4;

    const int bz = blockIdx.z;
    Ahi += bz * sA; Alo += bz * sA;
    Bhi += bz * sB; Blo += bz * sB;
    if (F32OUT) Cf += bz * sC;
    const int m0 = blockIdx.y * 128;
    const int n0 = blockIdx.x * 128;

    const u32 smem_base = smem_u32(smem);

    float acc[4][4][4];
#pragma unroll
    for (int mi = 0; mi < 4; mi++)
#pragma unroll
        for (int ni = 0; ni < 4; ni++)
#pragma unroll
            for (int c = 0; c < 4; c++) acc[mi][ni][c] = 0.0f;

    const int NC = K >> 5;   // k-chunks of 32

    // ---- async stage loader: 4 planes (Ahi, Alo, Bhi, Blo), each 128x32 bf16
    auto issue_stage = [&](int c) {
        const int k0 = c * 32;
        const u32 st = smem_base + (c & 1) * STAGE_B;
        const u16* srcs[4] = { Ahi, Alo, Bhi, Blo };
#pragma unroll
        for (int p = 0; p < 4; p++) {
            const u16* src = srcs[p];
            const int rbase = (p < 2) ? m0 : n0;
#pragma unroll
            for (int i = 0; i < 2; i++) {
                const int idx = tid + i * 256;
                const int row = idx >> 2;
                const int ch  = idx & 3;
                cp_async16(st + p * PLANE_B + row * TROW_B + ch * 16,
                           src + (long long)(rbase + row) * K + k0 + ch * 8);
            }
        }
        CP_COMMIT();
    };

    issue_stage(0);
    issue_stage(1);

    for (int c = 0; c < NC; ++c) {
        CP_WAIT1();
        __syncthreads();

        const u32 st = smem_base + (c & 1) * STAGE_B;

#pragma unroll
        for (int half = 0; half < 2; half++) {
            const u32 choff = (u32)(half * 2 + lch) * 16;

            // ---- B fragments: 2 x ldmatrix.x4 per plane cover all 4 ni ----
            u32 bh[4][2], bl[4][2];
#pragma unroll
            for (int nj = 0; nj < 2; nj++) {
                const u32 rb = (u32)(wn * 32 + nj * 16 + lrow) * TROW_B + choff;
                u32 r0, r1, r2, r3;
                ldmat4(r0, r1, r2, r3, st + 2 * PLANE_B + rb);
                bh[2*nj][0] = r0; bh[2*nj+1][0] = r1;
                bh[2*nj][1] = r2; bh[2*nj+1][1] = r3;
                ldmat4(r0, r1, r2, r3, st + 3 * PLANE_B + rb);
                bl[2*nj][0] = r0; bl[2*nj+1][0] = r1;
                bl[2*nj][1] = r2; bl[2*nj+1][1] = r3;
            }

            // ---- A fragments + 3-term MMAs ----
#pragma unroll
            for (int mi = 0; mi < 4; mi++) {
                const u32 ra = (u32)(wm * 64 + mi * 16 + lrow) * TROW_B + choff;
                u32 ah[4], al[4];
                ldmat4(ah[0], ah[1], ah[2], ah[3], st + ra);
                ldmat4(al[0], al[1], al[2], al[3], st + PLANE_B + ra);
#pragma unroll
                for (int ni = 0; ni < 4; ni++) {
                    mma_bf16(acc[mi][ni], ah, bh[ni]);
                    mma_bf16(acc[mi][ni], ah, bl[ni]);
                    mma_bf16(acc[mi][ni], al, bh[ni]);
                }
            }
        }

        __syncthreads();
        if (c + 2 < NC) issue_stage(c + 2);
        else            CP_COMMIT();   // keep group accounting uniform
    }

    // ---- epilogue ----
#pragma unroll
    for (int mi = 0; mi < 4; mi++) {
        const int m_lo = m0 + wm * 64 + mi * 16 + g;
        const int m_hi = m_lo + 8;
        const float* pe_lo = posenc ? posenc + (long long)(m_lo & (SEQL - 1)) * N : 0;
        const float* pe_hi = posenc ? posenc + (long long)(m_hi & (SEQL - 1)) * N : 0;
#pragma unroll
        for (int ni = 0; ni < 4; ni++) {
            const int n = n0 + wn * 32 + ni * 8 + 2 * t;
            float2 v0, v1;
            v0.x = acc[mi][ni][0] * alpha;
            v0.y = acc[mi][ni][1] * alpha;
            v1.x = acc[mi][ni][2] * alpha;
            v1.y = acc[mi][ni][3] * alpha;
            if (bias) {
                const float b0 = bias[n], b1 = bias[n + 1];
                v0.x += b0; v0.y += b1;
                v1.x += b0; v1.y += b1;
            }
            if (posenc) {
                v0.x += pe_lo[n]; v0.y += pe_lo[n + 1];
                v1.x += pe_hi[n]; v1.y += pe_hi[n + 1];
            }
            if (F32OUT) {
                *(float2*)(Cf + (long long)m_lo * N + n) = v0;
                *(float2*)(Cf + (long long)m_hi * N + n) = v1;
            }
            if (SPLITOUT) {
                u32 h, l;
                if (!TRANSOUT) {
                    split_pack(v0.x, v0.y, h, l);
                    *(u32*)(Chi + (long long)m_lo * N + n) = h;
                    *(u32*)(Clo + (long long)m_lo * N + n) = l;
                    split_pack(v1.x, v1.y, h, l);
                    *(u32*)(Chi + (long long)m_hi * N + n) = h;
                    *(u32*)(Clo + (long long)m_hi * N + n) = l;
                } else {
                    // V^T: out[b][n][s], m = b*SEQL + s; DMODEL*SEQL = 1<<21
                    const long long base_lo =
                        ((long long)(m_lo >> 11) << 21) + (m_lo & 2047);
                    const long long base_hi =
                        ((long long)(m_hi >> 11) << 21) + (m_hi & 2047);
                    split_pack(v0.x, v0.y, h, l);
                    Chi[base_lo + (long long)n * SEQL]       = (u16)h;
                    Chi[base_lo + (long long)(n + 1) * SEQL] = (u16)(h >> 16);
                    Clo[base_lo + (long long)n * SEQL]       = (u16)l;
                    Clo[base_lo + (long long)(n + 1) * SEQL] = (u16)(l >> 16);
                    split_pack(v1.x, v1.y, h, l);
                    Chi[base_hi + (long long)n * SEQL]       = (u16)h;
                    Chi[base_hi + (long long)(n + 1) * SEQL] = (u16)(h >> 16);
                    Clo[base_hi + (long long)n * SEQL]       = (u16)l;
                    Clo[base_hi + (long long)(n + 1) * SEQL] = (u16)(l >> 16);
                }
            }
        }
    }
}

// ---------------------------------------------------------------------------
// fp32 -> split bf16 hi/lo planes (4 elems per thread)
// ---------------------------------------------------------------------------
__global__ void split_fp32(const float* __restrict__ src,
                           u16* __restrict__ hi, u16* __restrict__ lo, int n4)
{
    const int i = blockIdx.x * blockDim.x + threadIdx.x;
    if (i >= n4) return;
    const float4 v = ((const float4*)src)[i];
    u32 h01, l01, h23, l23;
    split_pack(v.x, v.y, h01, l01);
    split_pack(v.z, v.w, h23, l23);
    ((uint2*)hi)[i] = make_uint2(h01, h23);
    ((uint2*)lo)[i] = make_uint2(l01, l23);
}

// ---------------------------------------------------------------------------
// Row softmax (2048 cols) reading fp32, writing split bf16 planes.
// ---------------------------------------------------------------------------
__global__ void softmax_split(const float* __restrict__ S,
                              u16* __restrict__ hi, u16* __restrict__ lo)
{
    const long long off = (long long)blockIdx.x * 2048;
    const float* row = S + off;
    const int tid = threadIdx.x;
    __shared__ float red[256];

    float v[8];
    *(float4*)&v[0] = *(const float4*)(row + tid * 8);
    *(float4*)&v[4] = *(const float4*)(row + tid * 8 + 4);

    float mx = -1e30f;
#pragma unroll
    for (int i = 0; i < 8; i++) mx = fmaxf(mx, v[i]);
    red[tid] = mx; __syncthreads();
    for (int s = 128; s > 0; s >>= 1) {
        if (tid < s) red[tid] = fmaxf(red[tid], red[tid + s]);
        __syncthreads();
    }
    mx = red[0]; __syncthreads();

    float sum = 0.0f;
#pragma unroll
    for (int i = 0; i < 8; i++) { v[i] = __expf(v[i] - mx); sum += v[i]; }
    red[tid] = sum; __syncthreads();
    for (int s = 128; s > 0; s >>= 1) {
        if (tid < s) red[tid] += red[tid + s];
        __syncthreads();
    }
    const float inv = 1.0f / red[0];

    u32* hp = (u32*)hi + (off >> 1) + tid * 4;
    u32* lp = (u32*)lo + (off >> 1) + tid * 4;
#pragma unroll
    for (int j = 0; j < 4; j++) {
        u32 h, l;
        split_pack(v[2*j] * inv, v[2*j+1] * inv, h, l);
        hp[j] = h; lp[j] = l;
    }
}

// ---------------------------------------------------------------------------
// Plain fp32 row softmax (for the length-2048 pooling weights, 8 rows)
// ---------------------------------------------------------------------------
__global__ void softmax_rows(float* __restrict__ S)
{
    float* row = S + (long long)blockIdx.x * 2048;
    const int tid = threadIdx.x;
    __shared__ float red[256];

    float v[8];
    *(float4*)&v[0] = *(const float4*)(row + tid * 8);
    *(float4*)&v[4] = *(const float4*)(row + tid * 8 + 4);

    float mx = -1e30f;
#pragma unroll
    for (int i = 0; i < 8; i++) mx = fmaxf(mx, v[i]);
    red[tid] = mx; __syncthreads();
    for (int s = 128; s > 0; s >>= 1) {
        if (tid < s) red[tid] = fmaxf(red[tid], red[tid + s]);
        __syncthreads();
    }
    mx = red[0]; __syncthreads();

    float sum = 0.0f;
#pragma unroll
    for (int i = 0; i < 8; i++) { v[i] = __expf(v[i] - mx); sum += v[i]; }
    red[tid] = sum; __syncthreads();
    for (int s = 128; s > 0; s >>= 1) {
        if (tid < s) red[tid] += red[tid + s];
        __syncthreads();
    }
    const float inv = 1.0f / red[0];
#pragma unroll
    for (int i = 0; i < 8; i++) v[i] *= inv;
    *(float4*)(row + tid * 8)     = *(float4*)&v[0];
    *(float4*)(row + tid * 8 + 4) = *(float4*)&v[4];
}

// ---------------------------------------------------------------------------
// h = x + z ; H = LN(h)*g + b  -> fp32 H + split planes
// ---------------------------------------------------------------------------
__global__ void add_ln_split(const float* __restrict__ X, const float* __restrict__ Z,
                             const float* __restrict__ g, const float* __restrict__ b,
                             float* __restrict__ H, u16* __restrict__ hi, u16* __restrict__ lo)
{
    const long long r = blockIdx.x;
    const int tid = threadIdx.x;
    const int c0  = tid * 4;
    const float* xr = X + r * DMODEL;
    const float* zr = Z + r * DMODEL;
    __shared__ float red[256];

    float4 x4 = *(const float4*)(xr + c0);
    float4 z4 = *(const float4*)(zr + c0);
    float h[4] = { x4.x + z4.x, x4.y + z4.y, x4.z + z4.z, x4.w + z4.w };

    float sum = h[0] + h[1] + h[2] + h[3];
    red[tid] = sum; __syncthreads();
    for (int s = 128; s > 0; s >>= 1) {
        if (tid < s) red[tid] += red[tid + s];
        __syncthreads();
    }
    const float mean = red[0] * (1.0f / DMODEL);
    __syncthreads();

    float vs = 0.0f;
#pragma unroll
    for (int i = 0; i < 4; i++) { const float d = h[i] - mean; vs += d * d; }
    red[tid] = vs; __syncthreads();
    for (int s = 128; s > 0; s >>= 1) {
        if (tid < s) red[tid] += red[tid + s];
        __syncthreads();
    }
    const float inv = rsqrtf(red[0] * (1.0f / DMODEL) + LN_EPS);

    float4 o;
    o.x = (h[0] - mean) * inv * g[c0 + 0] + b[c0 + 0];
    o.y = (h[1] - mean) * inv * g[c0 + 1] + b[c0 + 1];
    o.z = (h[2] - mean) * inv * g[c0 + 2] + b[c0 + 2];
    o.w = (h[3] - mean) * inv * g[c0 + 3] + b[c0 + 3];
    *(float4*)(H + r * DMODEL + c0) = o;

    u32 h01, l01, h23, l23;
    split_pack(o.x, o.y, h01, l01);
    split_pack(o.z, o.w, h23, l23);
    const long long pi = (r * DMODEL + c0) >> 1;
    ((u32*)hi)[pi]     = h01;
    ((u32*)hi)[pi + 1] = h23;
    ((u32*)lo)[pi]     = l01;
    ((u32*)lo)[pi + 1] = l23;
}

// ---------------------------------------------------------------------------
// t[r] = sum_o tanh(SK[r,o]) * q[o]
// ---------------------------------------------------------------------------
__global__ void softkey_reduce(const float* __restrict__ SK, const float* __restrict__ q,
                               float* __restrict__ t)
{
    const long long r = blockIdx.x;
    const int tid = threadIdx.x;
    __shared__ float red[256];

    float s = 0.0f;
#pragma unroll
    for (int i = 0; i < 4; i++) {
        const int c = tid + i * 256;
        s += tanhf(SK[r * DMODEL + c]) * q[c];
    }
    red[tid] = s; __syncthreads();
    for (int k = 128; k > 0; k >>= 1) {
        if (tid < k) red[tid] += red[tid + k];
        __syncthreads();
    }
    if (tid == 0) t[r] = red[0];
}

// ---------------------------------------------------------------------------
// out[b,o] = sum_s w[b,s] * H[b,s,o]
// ---------------------------------------------------------------------------
__global__ void final_out(const float* __restrict__ H, const float* __restrict__ w,
                          float* __restrict__ out)
{
    const int b = blockIdx.y;
    const int o = blockIdx.x * 256 + threadIdx.x;
    const float* Hb = H + (long long)b * SEQL * DMODEL;
    const float* wb = w + (long long)b * SEQL;

    float a0 = 0.0f, a1 = 0.0f, a2 = 0.0f, a3 = 0.0f;
    for (int s = 0; s < SEQL; s += 4) {
        a0 += wb[s + 0] * Hb[(long long)(s + 0) * DMODEL + o];
        a1 += wb[s + 1] * Hb[(long long)(s + 1) * DMODEL + o];
        a2 += wb[s + 2] * Hb[(long long)(s + 2) * DMODEL + o];
        a3 += wb[s + 3] * Hb[(long long)(s + 3) * DMODEL + o];
    }
    out[b * DMODEL + o] = (a0 + a1) + (a2 + a3);
}

// ---------------------------------------------------------------------------
// Launch
// ---------------------------------------------------------------------------
extern "C" void kernel_launch(void* const* d_in, const int* in_sizes, int n_in,
                              void* d_out, int out_size)
{
    const float* inputs  = (const float*)d_in[0];
    const float* embed_w = (const float*)d_in[1];
    const float* embed_b = (const float*)d_in[2];
    const float* wq_w    = (const float*)d_in[3];
    const float* wq_b    = (const float*)d_in[4];
    const float* wk_w    = (const float*)d_in[5];
    const float* wk_b    = (const float*)d_in[6];
    const float* wv_w    = (const float*)d_in[7];
    const float* wv_b    = (const float*)d_in[8];
    const float* ln_g    = (const float*)d_in[9];
    const float* ln_b    = (const float*)d_in[10];
    const float* skw     = (const float*)d_in[11];
    const float* sq      = (const float*)d_in[12];
    const float* pos     = (const float*)d_in[13];
    float* out = (float*)d_out;

    cudaFuncSetAttribute((const void*)tc_gemm<true,  true,  false>,
                         cudaFuncAttributeMaxDynamicSharedMemorySize, DYN_SMEM_G);
    cudaFuncSetAttribute((const void*)tc_gemm<false, true,  false>,
                         cudaFuncAttributeMaxDynamicSharedMemorySize, DYN_SMEM_G);
    cudaFuncSetAttribute((const void*)tc_gemm<false, true,  true>,
                         cudaFuncAttributeMaxDynamicSharedMemorySize, DYN_SMEM_G);
    cudaFuncSetAttribute((const void*)tc_gemm<true,  false, false>,
                         cudaFuncAttributeMaxDynamicSharedMemorySize, DYN_SMEM_G);

    float* base = 0;
    cudaGetSymbolAddress((void**)&base, g_scratch);

    u16* INh  = (u16*)(base + O_INS);   u16* INl  = INh  + C_IN;
    u16* EWh  = (u16*)(base + O_EWS);   u16* EWl  = EWh  + C_EW;
    u16* WQh  = (u16*)(base + O_WQS);   u16* WQl  = WQh  + C_W;
    u16* WKh  = (u16*)(base + O_WKS);   u16* WKl  = WKh  + C_W;
    u16* WVh  = (u16*)(base + O_WVS);   u16* WVl  = WVh  + C_W;
    u16* SKWh = (u16*)(base + O_SKWS);  u16* SKWl = SKWh + C_W;
    float* X  = base + O_X;
    u16* Xh   = (u16*)(base + O_XS);    u16* Xl   = Xh   + C_MAT;
    u16* Qh   = (u16*)(base + O_QS);    u16* Ql   = Qh   + C_MAT;
    u16* Kh   = (u16*)(base + O_KS);    u16* Kl   = Kh   + C_MAT;
    u16* VTh  = (u16*)(base + O_VTS);   u16* VTl  = VTh  + C_MAT;
    float* SC = base + O_SC;
    u16* SCh  = (u16*)(base + O_SCS);   u16* SCl  = SCh  + C_SC;
    float* Z  = base + O_Z;
    float* H  = base + O_H;
    u16* Hh   = (u16*)(base + O_HS);    u16* Hl   = Hh   + C_MAT;
    float* SK = base + O_SK;
    float* T  = base + O_T;

    // 0) one-time splits of raw inputs & weights
    split_fp32<<<(int)(C_IN / 4 / 256), 256>>>(inputs,  INh,  INl,  (int)(C_IN / 4));
    split_fp32<<<(int)(C_EW / 4 / 256), 256>>>(embed_w, EWh,  EWl,  (int)(C_EW / 4));
    split_fp32<<<(int)(C_W  / 4 / 256), 256>>>(wq_w,    WQh,  WQl,  (int)(C_W  / 4));
    split_fp32<<<(int)(C_W  / 4 / 256), 256>>>(wk_w,    WKh,  WKl,  (int)(C_W  / 4));
    split_fp32<<<(int)(C_W  / 4 / 256), 256>>>(wv_w,    WVh,  WVl,  (int)(C_W  / 4));
    split_fp32<<<(int)(C_W  / 4 / 256), 256>>>(skw,     SKWh, SKWl, (int)(C_W  / 4));

    // 1) embed: X = inputs @ embed_w^T + embed_b + pos_enc  (fp32 + split out)
    tc_gemm<true, true, false><<<dim3(DMODEL / 128, NROW / 128, 1), 256, DYN_SMEM_G>>>(
        INh, INl, EWh, EWl, X, Xh, Xl,
        NROW, DMODEL, D_IN, 0, 0, 0, 1.0f, embed_b, pos);

    // 2) Q, K (split out), V (transposed split out)
    tc_gemm<false, true, false><<<dim3(DMODEL / 128, NROW / 128, 1), 256, DYN_SMEM_G>>>(
        Xh, Xl, WQh, WQl, 0, Qh, Ql,
        NROW, DMODEL, DMODEL, 0, 0, 0, 1.0f, wq_b, 0);
    tc_gemm<false, true, false><<<dim3(DMODEL / 128, NROW / 128, 1), 256, DYN_SMEM_G>>>(
        Xh, Xl, WKh, WKl, 0, Kh, Kl,
        NROW, DMODEL, DMODEL, 0, 0, 0, 1.0f, wk_b, 0);
    tc_gemm<false, true, true><<<dim3(DMODEL / 128, NROW / 128, 1), 256, DYN_SMEM_G>>>(
        Xh, Xl, WVh, WVl, 0, VTh, VTl,
        NROW, DMODEL, DMODEL, 0, 0, 0, 1.0f, wv_b, 0);

    // 3) scores = Q @ K^T / 32 (batched, fp32 out)
    tc_gemm<true, false, false><<<dim3(SEQL / 128, SEQL / 128, BATCH), 256, DYN_SMEM_G>>>(
        Qh, Ql, Kh, Kl, SC, 0, 0,
        SEQL, SEQL, DMODEL,
        (long long)SEQL * DMODEL, (long long)SEQL * DMODEL, (long long)SEQL * SEQL,
        1.0f / 32.0f, 0, 0);

    // 4) softmax -> split planes
    softmax_split<<<NROW, 256>>>(SC, SCh, SCl);

    // 5) Z = softmax(SC) @ V  (B = V^T planes, [n][k] per batch)
    tc_gemm<true, false, false><<<dim3(DMODEL / 128, SEQL / 128, BATCH), 256, DYN_SMEM_G>>>(
        SCh, SCl, VTh, VTl, Z, 0, 0,
        SEQL, DMODEL, SEQL,
        (long long)SEQL * SEQL, (long long)DMODEL * SEQL, (long long)SEQL * DMODEL,
        1.0f, 0, 0);

    // 6) H = LN(X + Z)*g + b  (fp32 + split)
    add_ln_split<<<NROW, 256>>>(X, Z, ln_g, ln_b, H, Hh, Hl);

    // 7) SK = H @ soft_key_w^T (fp32 out)
    tc_gemm<true, false, false><<<dim3(DMODEL / 128, NROW / 128, 1), 256, DYN_SMEM_G>>>(
        Hh, Hl, SKWh, SKWl, SK, 0, 0,
        NROW, DMODEL, DMODEL, 0, 0, 0, 1.0f, 0, 0);

    // 8) t[b,s] = sum_o tanh(SK)*soft_query[o]; softmax over s per batch
    softkey_reduce<<<NROW, 256>>>(SK, sq, T);
    softmax_rows<<<BATCH, 256>>>(T);

    // 9) out[b,o] = sum_s w[b,s] * H[b,s,o]
    final_out<<<dim3(DMODEL / 256, BATCH), 256>>>(H, T, out);
}

// round 6
// speedup vs baseline: 1.0191x; 1.0191x over previous
#include <cuda_runtime.h>
#include <cstdint>
#include <math.h>

// ---------------------------------------------------------------------------
// Problem constants
// ---------------------------------------------------------------------------
#define BATCH   8
#define SEQL    2048
#define D_IN    512
#define DMODEL  1024
#define NROW    (BATCH * SEQL)          // 16384
#define LN_EPS  1e-5f

typedef unsigned short u16;
typedef uint32_t u32;

// element counts
static const long long C_IN  = (long long)NROW * D_IN;       // 8388608
static const long long C_EW  = (long long)DMODEL * D_IN;     // 524288
static const long long C_W   = (long long)DMODEL * DMODEL;   // 1048576
static const long long C_MAT = (long long)NROW * DMODEL;     // 16777216
static const long long C_SC  = (long long)BATCH * SEQL * SEQL; // 33554432

// scratch offsets (in floats; a split hi+lo pair of N elems occupies N floats)
#define O_INS   (0LL)
#define O_EWS   (O_INS  + C_IN)
#define O_WQS   (O_EWS  + C_EW)
#define O_WKS   (O_WQS  + C_W)
#define O_WVS   (O_WKS  + C_W)
#define O_SKWS  (O_WVS  + C_W)
#define O_X     (O_SKWS + C_W)
#define O_XS    (O_X    + C_MAT)
#define O_QS    (O_XS   + C_MAT)
#define O_KS    (O_QS   + C_MAT)
#define O_VTS   (O_KS   + C_MAT)
#define O_SC    (O_VTS  + C_MAT)
#define O_SCS   (O_SC   + C_SC)
#define O_Z     (O_SCS  + C_SC)
#define O_H     (O_Z    + C_MAT)
#define O_HS    (O_H    + C_MAT)
#define O_SK    (O_HS   + C_MAT)
#define O_T     (O_SK   + C_MAT)
#define O_TOTAL (O_T    + 16384)

__device__ float g_scratch[O_TOTAL];

// ---------------------------------------------------------------------------
// PTX helpers (baseline sm_80+ features only — harness targets plain sm_103)
// ---------------------------------------------------------------------------
__device__ __forceinline__ u32 smem_u32(const void* p) {
    u32 a;
    asm("{ .reg .u64 t; cvta.to.shared.u64 t, %1; cvt.u32.u64 %0, t; }"
        : "=r"(a) : "l"(p));
    return a;
}

__device__ __forceinline__ void cp_async16(u32 dst, const void* src) {
    asm volatile("cp.async.cg.shared.global [%0], [%1], 16;" :: "r"(dst), "l"(src));
}
#define CP_COMMIT() asm volatile("cp.async.commit_group;" ::: "memory")
#define CP_WAIT1()  asm volatile("cp.async.wait_group 1;"  ::: "memory")

// split x0,x1 (fp32) into packed bf16x2 hi and lo parts: x = hi + lo
__device__ __forceinline__ void split_pack(float x0, float x1, u32& hi, u32& lo) {
    asm("cvt.rn.bf16x2.f32 %0, %1, %2;" : "=r"(hi) : "f"(x1), "f"(x0));
    const float h0 = __uint_as_float(hi << 16);
    const float h1 = __uint_as_float(hi & 0xFFFF0000u);
    const float l0 = x0 - h0;
    const float l1 = x1 - h1;
    asm("cvt.rn.bf16x2.f32 %0, %1, %2;" : "=r"(lo) : "f"(l1), "f"(l0));
}

// D += A*B  (m16n8k16 bf16, fp32 accum)
__device__ __forceinline__ void mma_bf16(float* d, const u32* a, const u32* b) {
    asm volatile(
        "mma.sync.aligned.m16n8k16.row.col.f32.bf16.bf16.f32 "
        "{%0,%1,%2,%3}, {%4,%5,%6,%7}, {%8,%9}, {%0,%1,%2,%3};"
        : "+f"(d[0]), "+f"(d[1]), "+f"(d[2]), "+f"(d[3])
        : "r"(a[0]), "r"(a[1]), "r"(a[2]), "r"(a[3]), "r"(b[0]), "r"(b[1]));
}

__device__ __forceinline__ void ldmat4(u32& r0, u32& r1, u32& r2, u32& r3, u32 addr) {
    asm volatile("ldmatrix.sync.aligned.m8n8.x4.shared.b16 {%0,%1,%2,%3}, [%4];"
                 : "=r"(r0), "=r"(r1), "=r"(r2), "=r"(r3) : "r"(addr));
}

// ---------------------------------------------------------------------------
// bf16x3 split GEMM on pre-split hi/lo planes:
//   C[m,n] = alpha * sum_k A[m,k]*B[n,k]  (+bias +posenc)
// A planes [M][K] bf16, B planes [N][K] bf16. Tile 128x128x32, 256 thr,
// 8 warps (2x4), warp tile 64x32. ldmatrix fragments, 2-stage cp.async.
// MMA schedule is term-major over (mi-pair x ni) blocks so dependent HMMAs
// on the same accumulator are >= 8 issues apart.
//   F32OUT:  write fp32 C
//   SPLITOUT: write bf16 hi/lo planes of C
//   TRANSOUT: (V only) split planes written transposed per batch:
//             out[b][n][s] with m = b*SEQL + s
// ---------------------------------------------------------------------------
#define TROW_B   80                     // bytes per smem tile row (64 data + 16 pad)
#define PLANE_B  (128 * TROW_B)         // 10240
#define STAGE_B  (4 * PLANE_B)          // 40960
#define DYN_SMEM_G (2 * STAGE_B)        // 81920

template <bool F32OUT, bool SPLITOUT, bool TRANSOUT>
__global__ __launch_bounds__(256, 2)
void tc_gemm(const u16* __restrict__ Ahi, const u16* __restrict__ Alo,
             const u16* __restrict__ Bhi, const u16* __restrict__ Blo,
             float* __restrict__ Cf, u16* __restrict__ Chi, u16* __restrict__ Clo,
             int M, int N, int K,
             long long sA, long long sB, long long sC,
             float alpha, const float* __restrict__ bias,
             const float* __restrict__ posenc)
{
    extern __shared__ char smem[];

    const int tid  = threadIdx.x;
    const int wid  = tid >> 5;
    const int lane = tid & 31;
    const int wm   = wid >> 2;       // 0..1 (M)
    const int wn   = wid & 3;        // 0..3 (N)
    const int g    = lane >> 2;      // groupID 0..7
    const int t    = lane & 3;       // threadID_in_group
    const int lrow = lane & 15;
    const int lch  = lane >> 4;

    const int bz = blockIdx.z;
    Ahi += bz * sA; Alo += bz * sA;
    Bhi += bz * sB; Blo += bz * sB;
    if (F32OUT) Cf += bz * sC;
    const int m0 = blockIdx.y * 128;
    const int n0 = blockIdx.x * 128;

    const u32 smem_base = smem_u32(smem);

    float acc[4][4][4];
#pragma unroll
    for (int mi = 0; mi < 4; mi++)
#pragma unroll
        for (int ni = 0; ni < 4; ni++)
#pragma unroll
            for (int c = 0; c < 4; c++) acc[mi][ni][c] = 0.0f;

    const int NC = K >> 5;   // k-chunks of 32

    // ---- async stage loader: 4 planes (Ahi, Alo, Bhi, Blo), each 128x32 bf16
    auto issue_stage = [&](int c) {
        const int k0 = c * 32;
        const u32 st = smem_base + (c & 1) * STAGE_B;
        const u16* srcs[4] = { Ahi, Alo, Bhi, Blo };
#pragma unroll
        for (int p = 0; p < 4; p++) {
            const u16* src = srcs[p];
            const int rbase = (p < 2) ? m0 : n0;
#pragma unroll
            for (int i = 0; i < 2; i++) {
                const int idx = tid + i * 256;
                const int row = idx >> 2;
                const int ch  = idx & 3;
                cp_async16(st + p * PLANE_B + row * TROW_B + ch * 16,
                           src + (long long)(rbase + row) * K + k0 + ch * 8);
            }
        }
        CP_COMMIT();
    };

    issue_stage(0);
    issue_stage(1);

    for (int c = 0; c < NC; ++c) {
        CP_WAIT1();
        __syncthreads();

        const u32 st = smem_base + (c & 1) * STAGE_B;

#pragma unroll
        for (int half = 0; half < 2; half++) {
            const u32 choff = (u32)(half * 2 + lch) * 16;

            // ---- B fragments: 2 x ldmatrix.x4 per plane cover all 4 ni ----
            u32 bh[4][2], bl[4][2];
#pragma unroll
            for (int nj = 0; nj < 2; nj++) {
                const u32 rb = (u32)(wn * 32 + nj * 16 + lrow) * TROW_B + choff;
                u32 r0, r1, r2, r3;
                ldmat4(r0, r1, r2, r3, st + 2 * PLANE_B + rb);
                bh[2*nj][0] = r0; bh[2*nj+1][0] = r1;
                bh[2*nj][1] = r2; bh[2*nj+1][1] = r3;
                ldmat4(r0, r1, r2, r3, st + 3 * PLANE_B + rb);
                bl[2*nj][0] = r0; bl[2*nj+1][0] = r1;
                bl[2*nj][1] = r2; bl[2*nj+1][1] = r3;
            }

            // ---- A fragments for an mi-pair, then term-major MMA blocks ----
#pragma unroll
            for (int mp = 0; mp < 2; mp++) {
                u32 ah[2][4], al[2][4];
#pragma unroll
                for (int q = 0; q < 2; q++) {
                    const int mi = mp * 2 + q;
                    const u32 ra = (u32)(wm * 64 + mi * 16 + lrow) * TROW_B + choff;
                    ldmat4(ah[q][0], ah[q][1], ah[q][2], ah[q][3], st + ra);
                    ldmat4(al[q][0], al[q][1], al[q][2], al[q][3], st + PLANE_B + ra);
                }
                // term 1: hi*hi — 8 independent MMAs
#pragma unroll
                for (int q = 0; q < 2; q++)
#pragma unroll
                    for (int ni = 0; ni < 4; ni++)
                        mma_bf16(acc[mp*2+q][ni], ah[q], bh[ni]);
                // term 2: hi*lo
#pragma unroll
                for (int q = 0; q < 2; q++)
#pragma unroll
                    for (int ni = 0; ni < 4; ni++)
                        mma_bf16(acc[mp*2+q][ni], ah[q], bl[ni]);
                // term 3: lo*hi
#pragma unroll
                for (int q = 0; q < 2; q++)
#pragma unroll
                    for (int ni = 0; ni < 4; ni++)
                        mma_bf16(acc[mp*2+q][ni], al[q], bh[ni]);
            }
        }

        __syncthreads();
        if (c + 2 < NC) issue_stage(c + 2);
        else            CP_COMMIT();   // keep group accounting uniform
    }

    // ---- epilogue ----
#pragma unroll
    for (int mi = 0; mi < 4; mi++) {
        const int m_lo = m0 + wm * 64 + mi * 16 + g;
        const int m_hi = m_lo + 8;
        const float* pe_lo = posenc ? posenc + (long long)(m_lo & (SEQL - 1)) * N : 0;
        const float* pe_hi = posenc ? posenc + (long long)(m_hi & (SEQL - 1)) * N : 0;
#pragma unroll
        for (int ni = 0; ni < 4; ni++) {
            const int n = n0 + wn * 32 + ni * 8 + 2 * t;
            float2 v0, v1;
            v0.x = acc[mi][ni][0] * alpha;
            v0.y = acc[mi][ni][1] * alpha;
            v1.x = acc[mi][ni][2] * alpha;
            v1.y = acc[mi][ni][3] * alpha;
            if (bias) {
                const float b0 = bias[n], b1 = bias[n + 1];
                v0.x += b0; v0.y += b1;
                v1.x += b0; v1.y += b1;
            }
            if (posenc) {
                v0.x += pe_lo[n]; v0.y += pe_lo[n + 1];
                v1.x += pe_hi[n]; v1.y += pe_hi[n + 1];
            }
            if (F32OUT) {
                *(float2*)(Cf + (long long)m_lo * N + n) = v0;
                *(float2*)(Cf + (long long)m_hi * N + n) = v1;
            }
            if (SPLITOUT) {
                u32 h, l;
                if (!TRANSOUT) {
                    split_pack(v0.x, v0.y, h, l);
                    *(u32*)(Chi + (long long)m_lo * N + n) = h;
                    *(u32*)(Clo + (long long)m_lo * N + n) = l;
                    split_pack(v1.x, v1.y, h, l);
                    *(u32*)(Chi + (long long)m_hi * N + n) = h;
                    *(u32*)(Clo + (long long)m_hi * N + n) = l;
                } else {
                    // V^T: out[b][n][s], m = b*SEQL + s; DMODEL*SEQL = 1<<21
                    const long long base_lo =
                        ((long long)(m_lo >> 11) << 21) + (m_lo & 2047);
                    const long long base_hi =
                        ((long long)(m_hi >> 11) << 21) + (m_hi & 2047);
                    split_pack(v0.x, v0.y, h, l);
                    Chi[base_lo + (long long)n * SEQL]       = (u16)h;
                    Chi[base_lo + (long long)(n + 1) * SEQL] = (u16)(h >> 16);
                    Clo[base_lo + (long long)n * SEQL]       = (u16)l;
                    Clo[base_lo + (long long)(n + 1) * SEQL] = (u16)(l >> 16);
                    split_pack(v1.x, v1.y, h, l);
                    Chi[base_hi + (long long)n * SEQL]       = (u16)h;
                    Chi[base_hi + (long long)(n + 1) * SEQL] = (u16)(h >> 16);
                    Clo[base_hi + (long long)n * SEQL]       = (u16)l;
                    Clo[base_hi + (long long)(n + 1) * SEQL] = (u16)(l >> 16);
                }
            }
        }
    }
}

// ---------------------------------------------------------------------------
// fp32 -> split bf16 hi/lo planes (4 elems per thread)
// ---------------------------------------------------------------------------
__global__ void split_fp32(const float* __restrict__ src,
                           u16* __restrict__ hi, u16* __restrict__ lo, int n4)
{
    const int i = blockIdx.x * blockDim.x + threadIdx.x;
    if (i >= n4) return;
    const float4 v = ((const float4*)src)[i];
    u32 h01, l01, h23, l23;
    split_pack(v.x, v.y, h01, l01);
    split_pack(v.z, v.w, h23, l23);
    ((uint2*)hi)[i] = make_uint2(h01, h23);
    ((uint2*)lo)[i] = make_uint2(l01, l23);
}

// ---------------------------------------------------------------------------
// Row softmax (2048 cols) reading fp32, writing split bf16 planes.
// ---------------------------------------------------------------------------
__global__ void softmax_split(const float* __restrict__ S,
                              u16* __restrict__ hi, u16* __restrict__ lo)
{
    const long long off = (long long)blockIdx.x * 2048;
    const float* row = S + off;
    const int tid = threadIdx.x;
    __shared__ float red[256];

    float v[8];
    *(float4*)&v[0] = *(const float4*)(row + tid * 8);
    *(float4*)&v[4] = *(const float4*)(row + tid * 8 + 4);

    float mx = -1e30f;
#pragma unroll
    for (int i = 0; i < 8; i++) mx = fmaxf(mx, v[i]);
    red[tid] = mx; __syncthreads();
    for (int s = 128; s > 0; s >>= 1) {
        if (tid < s) red[tid] = fmaxf(red[tid], red[tid + s]);
        __syncthreads();
    }
    mx = red[0]; __syncthreads();

    float sum = 0.0f;
#pragma unroll
    for (int i = 0; i < 8; i++) { v[i] = __expf(v[i] - mx); sum += v[i]; }
    red[tid] = sum; __syncthreads();
    for (int s = 128; s > 0; s >>= 1) {
        if (tid < s) red[tid] += red[tid + s];
        __syncthreads();
    }
    const float inv = 1.0f / red[0];

    u32* hp = (u32*)hi + (off >> 1) + tid * 4;
    u32* lp = (u32*)lo + (off >> 1) + tid * 4;
#pragma unroll
    for (int j = 0; j < 4; j++) {
        u32 h, l;
        split_pack(v[2*j] * inv, v[2*j+1] * inv, h, l);
        hp[j] = h; lp[j] = l;
    }
}

// ---------------------------------------------------------------------------
// Plain fp32 row softmax (for the length-2048 pooling weights, 8 rows)
// ---------------------------------------------------------------------------
__global__ void softmax_rows(float* __restrict__ S)
{
    float* row = S + (long long)blockIdx.x * 2048;
    const int tid = threadIdx.x;
    __shared__ float red[256];

    float v[8];
    *(float4*)&v[0] = *(const float4*)(row + tid * 8);
    *(float4*)&v[4] = *(const float4*)(row + tid * 8 + 4);

    float mx = -1e30f;
#pragma unroll
    for (int i = 0; i < 8; i++) mx = fmaxf(mx, v[i]);
    red[tid] = mx; __syncthreads();
    for (int s = 128; s > 0; s >>= 1) {
        if (tid < s) red[tid] = fmaxf(red[tid], red[tid + s]);
        __syncthreads();
    }
    mx = red[0]; __syncthreads();

    float sum = 0.0f;
#pragma unroll
    for (int i = 0; i < 8; i++) { v[i] = __expf(v[i] - mx); sum += v[i]; }
    red[tid] = sum; __syncthreads();
    for (int s = 128; s > 0; s >>= 1) {
        if (tid < s) red[tid] += red[tid + s];
        __syncthreads();
    }
    const float inv = 1.0f / red[0];
#pragma unroll
    for (int i = 0; i < 8; i++) v[i] *= inv;
    *(float4*)(row + tid * 8)     = *(float4*)&v[0];
    *(float4*)(row + tid * 8 + 4) = *(float4*)&v[4];
}

// ---------------------------------------------------------------------------
// h = x + z ; H = LN(h)*g + b  -> fp32 H + split planes
// ---------------------------------------------------------------------------
__global__ void add_ln_split(const float* __restrict__ X, const float* __restrict__ Z,
                             const float* __restrict__ g, const float* __restrict__ b,
                             float* __restrict__ H, u16* __restrict__ hi, u16* __restrict__ lo)
{
    const long long r = blockIdx.x;
    const int tid = threadIdx.x;
    const int c0  = tid * 4;
    const float* xr = X + r * DMODEL;
    const float* zr = Z + r * DMODEL;
    __shared__ float red[256];

    float4 x4 = *(const float4*)(xr + c0);
    float4 z4 = *(const float4*)(zr + c0);
    float h[4] = { x4.x + z4.x, x4.y + z4.y, x4.z + z4.z, x4.w + z4.w };

    float sum = h[0] + h[1] + h[2] + h[3];
    red[tid] = sum; __syncthreads();
    for (int s = 128; s > 0; s >>= 1) {
        if (tid < s) red[tid] += red[tid + s];
        __syncthreads();
    }
    const float mean = red[0] * (1.0f / DMODEL);
    __syncthreads();

    float vs = 0.0f;
#pragma unroll
    for (int i = 0; i < 4; i++) { const float d = h[i] - mean; vs += d * d; }
    red[tid] = vs; __syncthreads();
    for (int s = 128; s > 0; s >>= 1) {
        if (tid < s) red[tid] += red[tid + s];
        __syncthreads();
    }
    const float inv = rsqrtf(red[0] * (1.0f / DMODEL) + LN_EPS);

    float4 o;
    o.x = (h[0] - mean) * inv * g[c0 + 0] + b[c0 + 0];
    o.y = (h[1] - mean) * inv * g[c0 + 1] + b[c0 + 1];
    o.z = (h[2] - mean) * inv * g[c0 + 2] + b[c0 + 2];
    o.w = (h[3] - mean) * inv * g[c0 + 3] + b[c0 + 3];
    *(float4*)(H + r * DMODEL + c0) = o;

    u32 h01, l01, h23, l23;
    split_pack(o.x, o.y, h01, l01);
    split_pack(o.z, o.w, h23, l23);
    const long long pi = (r * DMODEL + c0) >> 1;
    ((u32*)hi)[pi]     = h01;
    ((u32*)hi)[pi + 1] = h23;
    ((u32*)lo)[pi]     = l01;
    ((u32*)lo)[pi + 1] = l23;
}

// ---------------------------------------------------------------------------
// t[r] = sum_o tanh(SK[r,o]) * q[o]
// ---------------------------------------------------------------------------
__global__ void softkey_reduce(const float* __restrict__ SK, const float* __restrict__ q,
                               float* __restrict__ t)
{
    const long long r = blockIdx.x;
    const int tid = threadIdx.x;
    __shared__ float red[256];

    float s = 0.0f;
#pragma unroll
    for (int i = 0; i < 4; i++) {
        const int c = tid + i * 256;
        s += tanhf(SK[r * DMODEL + c]) * q[c];
    }
    red[tid] = s; __syncthreads();
    for (int k = 128; k > 0; k >>= 1) {
        if (tid < k) red[tid] += red[tid + k];
        __syncthreads();
    }
    if (tid == 0) t[r] = red[0];
}

// ---------------------------------------------------------------------------
// out[b,o] = sum_s w[b,s] * H[b,s,o]
// ---------------------------------------------------------------------------
__global__ void final_out(const float* __restrict__ H, const float* __restrict__ w,
                          float* __restrict__ out)
{
    const int b = blockIdx.y;
    const int o = blockIdx.x * 256 + threadIdx.x;
    const float* Hb = H + (long long)b * SEQL * DMODEL;
    const float* wb = w + (long long)b * SEQL;

    float a0 = 0.0f, a1 = 0.0f, a2 = 0.0f, a3 = 0.0f;
    for (int s = 0; s < SEQL; s += 4) {
        a0 += wb[s + 0] * Hb[(long long)(s + 0) * DMODEL + o];
        a1 += wb[s + 1] * Hb[(long long)(s + 1) * DMODEL + o];
        a2 += wb[s + 2] * Hb[(long long)(s + 2) * DMODEL + o];
        a3 += wb[s + 3] * Hb[(long long)(s + 3) * DMODEL + o];
    }
    out[b * DMODEL + o] = (a0 + a1) + (a2 + a3);
}

// ---------------------------------------------------------------------------
// Launch
// ---------------------------------------------------------------------------
extern "C" void kernel_launch(void* const* d_in, const int* in_sizes, int n_in,
                              void* d_out, int out_size)
{
    const float* inputs  = (const float*)d_in[0];
    const float* embed_w = (const float*)d_in[1];
    const float* embed_b = (const float*)d_in[2];
    const float* wq_w    = (const float*)d_in[3];
    const float* wq_b    = (const float*)d_in[4];
    const float* wk_w    = (const float*)d_in[5];
    const float* wk_b    = (const float*)d_in[6];
    const float* wv_w    = (const float*)d_in[7];
    const float* wv_b    = (const float*)d_in[8];
    const float* ln_g    = (const float*)d_in[9];
    const float* ln_b    = (const float*)d_in[10];
    const float* skw     = (const float*)d_in[11];
    const float* sq      = (const float*)d_in[12];
    const float* pos     = (const float*)d_in[13];
    float* out = (float*)d_out;

    cudaFuncSetAttribute((const void*)tc_gemm<true,  true,  false>,
                         cudaFuncAttributeMaxDynamicSharedMemorySize, DYN_SMEM_G);
    cudaFuncSetAttribute((const void*)tc_gemm<false, true,  false>,
                         cudaFuncAttributeMaxDynamicSharedMemorySize, DYN_SMEM_G);
    cudaFuncSetAttribute((const void*)tc_gemm<false, true,  true>,
                         cudaFuncAttributeMaxDynamicSharedMemorySize, DYN_SMEM_G);
    cudaFuncSetAttribute((const void*)tc_gemm<true,  false, false>,
                         cudaFuncAttributeMaxDynamicSharedMemorySize, DYN_SMEM_G);

    float* base = 0;
    cudaGetSymbolAddress((void**)&base, g_scratch);

    u16* INh  = (u16*)(base + O_INS);   u16* INl  = INh  + C_IN;
    u16* EWh  = (u16*)(base + O_EWS);   u16* EWl  = EWh  + C_EW;
    u16* WQh  = (u16*)(base + O_WQS);   u16* WQl  = WQh  + C_W;
    u16* WKh  = (u16*)(base + O_WKS);   u16* WKl  = WKh  + C_W;
    u16* WVh  = (u16*)(base + O_WVS);   u16* WVl  = WVh  + C_W;
    u16* SKWh = (u16*)(base + O_SKWS);  u16* SKWl = SKWh + C_W;
    float* X  = base + O_X;
    u16* Xh   = (u16*)(base + O_XS);    u16* Xl   = Xh   + C_MAT;
    u16* Qh   = (u16*)(base + O_QS);    u16* Ql   = Qh   + C_MAT;
    u16* Kh   = (u16*)(base + O_KS);    u16* Kl   = Kh   + C_MAT;
    u16* VTh  = (u16*)(base + O_VTS);   u16* VTl  = VTh  + C_MAT;
    float* SC = base + O_SC;
    u16* SCh  = (u16*)(base + O_SCS);   u16* SCl  = SCh  + C_SC;
    float* Z  = base + O_Z;
    float* H  = base + O_H;
    u16* Hh   = (u16*)(base + O_HS);    u16* Hl   = Hh   + C_MAT;
    float* SK = base + O_SK;
    float* T  = base + O_T;

    // 0) one-time splits of raw inputs & weights
    split_fp32<<<(int)(C_IN / 4 / 256), 256>>>(inputs,  INh,  INl,  (int)(C_IN / 4));
    split_fp32<<<(int)(C_EW / 4 / 256), 256>>>(embed_w, EWh,  EWl,  (int)(C_EW / 4));
    split_fp32<<<(int)(C_W  / 4 / 256), 256>>>(wq_w,    WQh,  WQl,  (int)(C_W  / 4));
    split_fp32<<<(int)(C_W  / 4 / 256), 256>>>(wk_w,    WKh,  WKl,  (int)(C_W  / 4));
    split_fp32<<<(int)(C_W  / 4 / 256), 256>>>(wv_w,    WVh,  WVl,  (int)(C_W  / 4));
    split_fp32<<<(int)(C_W  / 4 / 256), 256>>>(skw,     SKWh, SKWl, (int)(C_W  / 4));

    // 1) embed: X = inputs @ embed_w^T + embed_b + pos_enc  (fp32 + split out)
    tc_gemm<true, true, false><<<dim3(DMODEL / 128, NROW / 128, 1), 256, DYN_SMEM_G>>>(
        INh, INl, EWh, EWl, X, Xh, Xl,
        NROW, DMODEL, D_IN, 0, 0, 0, 1.0f, embed_b, pos);

    // 2) Q, K (split out), V (transposed split out)
    tc_gemm<false, true, false><<<dim3(DMODEL / 128, NROW / 128, 1), 256, DYN_SMEM_G>>>(
        Xh, Xl, WQh, WQl, 0, Qh, Ql,
        NROW, DMODEL, DMODEL, 0, 0, 0, 1.0f, wq_b, 0);
    tc_gemm<false, true, false><<<dim3(DMODEL / 128, NROW / 128, 1), 256, DYN_SMEM_G>>>(
        Xh, Xl, WKh, WKl, 0, Kh, Kl,
        NROW, DMODEL, DMODEL, 0, 0, 0, 1.0f, wk_b, 0);
    tc_gemm<false, true, true><<<dim3(DMODEL / 128, NROW / 128, 1), 256, DYN_SMEM_G>>>(
        Xh, Xl, WVh, WVl, 0, VTh, VTl,
        NROW, DMODEL, DMODEL, 0, 0, 0, 1.0f, wv_b, 0);

    // 3) scores = Q @ K^T / 32 (batched, fp32 out)
    tc_gemm<true, false, false><<<dim3(SEQL / 128, SEQL / 128, BATCH), 256, DYN_SMEM_G>>>(
        Qh, Ql, Kh, Kl, SC, 0, 0,
        SEQL, SEQL, DMODEL,
        (long long)SEQL * DMODEL, (long long)SEQL * DMODEL, (long long)SEQL * SEQL,
        1.0f / 32.0f, 0, 0);

    // 4) softmax -> split planes
    softmax_split<<<NROW, 256>>>(SC, SCh, SCl);

    // 5) Z = softmax(SC) @ V  (B = V^T planes, [n][k] per batch)
    tc_gemm<true, false, false><<<dim3(DMODEL / 128, SEQL / 128, BATCH), 256, DYN_SMEM_G>>>(
        SCh, SCl, VTh, VTl, Z, 0, 0,
        SEQL, DMODEL, SEQL,
        (long long)SEQL * SEQL, (long long)DMODEL * SEQL, (long long)SEQL * DMODEL,
        1.0f, 0, 0);

    // 6) H = LN(X + Z)*g + b  (fp32 + split)
    add_ln_split<<<NROW, 256>>>(X, Z, ln_g, ln_b, H, Hh, Hl);

    // 7) SK = H @ soft_key_w^T (fp32 out)
    tc_gemm<true, false, false><<<dim3(DMODEL / 128, NROW / 128, 1), 256, DYN_SMEM_G>>>(
        Hh, Hl, SKWh, SKWl, SK, 0, 0,
        NROW, DMODEL, DMODEL, 0, 0, 0, 1.0f, 0, 0);

    // 8) t[b,s] = sum_o tanh(SK)*soft_query[o]; softmax over s per batch
    softkey_reduce<<<NROW, 256>>>(SK, sq, T);
    softmax_rows<<<BATCH, 256>>>(T);

    // 9) out[b,o] = sum_s w[b,s] * H[b,s,o]
    final_out<<<dim3(DMODEL / 256, BATCH), 256>>>(H, T, out);
}

// round 7
// speedup vs baseline: 1.1807x; 1.1586x over previous
#include <cuda_runtime.h>
#include <cstdint>
#include <math.h>

// ---------------------------------------------------------------------------
// Problem constants
// ---------------------------------------------------------------------------
#define BATCH   8
#define SEQL    2048
#define D_IN    512
#define DMODEL  1024
#define NROW    (BATCH * SEQL)          // 16384
#define LN_EPS  1e-5f

typedef unsigned short u16;
typedef uint32_t u32;

// element counts
static const long long C_IN  = (long long)NROW * D_IN;       // 8388608
static const long long C_EW  = (long long)DMODEL * D_IN;     // 524288
static const long long C_W   = (long long)DMODEL * DMODEL;   // 1048576
static const long long C_MAT = (long long)NROW * DMODEL;     // 16777216
static const long long C_SC  = (long long)BATCH * SEQL * SEQL; // 33554432

// scratch offsets (in floats; a split hi+lo pair of N elems occupies N floats)
#define O_INS   (0LL)
#define O_EWS   (O_INS  + C_IN)
#define O_WQS   (O_EWS  + C_EW)
#define O_WKS   (O_WQS  + C_W)
#define O_WVS   (O_WKS  + C_W)
#define O_SKWS  (O_WVS  + C_W)
#define O_X     (O_SKWS + C_W)
#define O_XS    (O_X    + C_MAT)
#define O_QS    (O_XS   + C_MAT)
#define O_KS    (O_QS   + C_MAT)
#define O_VTS   (O_KS   + C_MAT)
#define O_SC    (O_VTS  + C_MAT)
#define O_SCS   (O_SC   + C_SC)
#define O_Z     (O_SCS  + C_SC)
#define O_H     (O_Z    + C_MAT)
#define O_HS    (O_H    + C_MAT)
#define O_SK    (O_HS   + C_MAT)
#define O_T     (O_SK   + C_MAT)
#define O_TOTAL (O_T    + 16384)

__device__ float g_scratch[O_TOTAL];

// ---------------------------------------------------------------------------
// PTX helpers (baseline sm_80+ features only — harness targets plain sm_103)
// ---------------------------------------------------------------------------
__device__ __forceinline__ u32 smem_u32(const void* p) {
    u32 a;
    asm("{ .reg .u64 t; cvta.to.shared.u64 t, %1; cvt.u32.u64 %0, t; }"
        : "=r"(a) : "l"(p));
    return a;
}

__device__ __forceinline__ void cp_async16(u32 dst, const void* src) {
    asm volatile("cp.async.cg.shared.global [%0], [%1], 16;" :: "r"(dst), "l"(src));
}
#define CP_COMMIT() asm volatile("cp.async.commit_group;" ::: "memory")
#define CP_WAIT1()  asm volatile("cp.async.wait_group 1;"  ::: "memory")

// split x0,x1 (fp32) into packed bf16x2 hi and lo parts: x = hi + lo
__device__ __forceinline__ void split_pack(float x0, float x1, u32& hi, u32& lo) {
    asm("cvt.rn.bf16x2.f32 %0, %1, %2;" : "=r"(hi) : "f"(x1), "f"(x0));
    const float h0 = __uint_as_float(hi << 16);
    const float h1 = __uint_as_float(hi & 0xFFFF0000u);
    const float l0 = x0 - h0;
    const float l1 = x1 - h1;
    asm("cvt.rn.bf16x2.f32 %0, %1, %2;" : "=r"(lo) : "f"(l1), "f"(l0));
}

// D += A*B  (m16n8k16 bf16, fp32 accum)
__device__ __forceinline__ void mma_bf16(float* d, const u32* a, const u32* b) {
    asm volatile(
        "mma.sync.aligned.m16n8k16.row.col.f32.bf16.bf16.f32 "
        "{%0,%1,%2,%3}, {%4,%5,%6,%7}, {%8,%9}, {%0,%1,%2,%3};"
        : "+f"(d[0]), "+f"(d[1]), "+f"(d[2]), "+f"(d[3])
        : "r"(a[0]), "r"(a[1]), "r"(a[2]), "r"(a[3]), "r"(b[0]), "r"(b[1]));
}

__device__ __forceinline__ void ldmat4(u32& r0, u32& r1, u32& r2, u32& r3, u32 addr) {
    asm volatile("ldmatrix.sync.aligned.m8n8.x4.shared.b16 {%0,%1,%2,%3}, [%4];"
                 : "=r"(r0), "=r"(r1), "=r"(r2), "=r"(r3) : "r"(addr));
}

// swizzled byte offset of (row, 16B-chunk ch) in a 128x32 bf16 plane (64B rows)
__device__ __forceinline__ u32 sw_off(u32 row, u32 ch) {
    return row * 64u + ((ch ^ ((row >> 1) & 3u)) << 4);
}

// ---------------------------------------------------------------------------
// bf16x3 split GEMM on pre-split hi/lo planes:
//   C[m,n] = alpha * sum_k A[m,k]*B[n,k]  (+bias +posenc)
// A planes [M][K] bf16, B planes [N][K] bf16. Tile 128x128x32, 256 thr,
// 8 warps (2x4), warp tile 64x32. ldmatrix fragments.
// 3-buffer cp.async pipeline, ONE __syncthreads per k-chunk.
// Stage layout: 4 planes (Ahi, Alo, Bhi, Blo) x 128 rows x 64B, XOR-swizzled.
//   F32OUT:  write fp32 C
//   SPLITOUT: write bf16 hi/lo planes of C
//   TRANSOUT: (V only) split planes written transposed per batch:
//             out[b][n][s] with m = b*SEQL + s
// ---------------------------------------------------------------------------
#define PLANE_B  (128 * 64)             // 8192
#define STAGE_B  (4 * PLANE_B)          // 32768
#define DYN_SMEM_G (3 * STAGE_B)        // 98304

template <bool F32OUT, bool SPLITOUT, bool TRANSOUT>
__global__ __launch_bounds__(256, 2)
void tc_gemm(const u16* __restrict__ Ahi, const u16* __restrict__ Alo,
             const u16* __restrict__ Bhi, const u16* __restrict__ Blo,
             float* __restrict__ Cf, u16* __restrict__ Chi, u16* __restrict__ Clo,
             int M, int N, int K,
             long long sA, long long sB, long long sC,
             float alpha, const float* __restrict__ bias,
             const float* __restrict__ posenc)
{
    extern __shared__ char smem[];

    const int tid  = threadIdx.x;
    const int wid  = tid >> 5;
    const int lane = tid & 31;
    const int wm   = wid >> 2;       // 0..1 (M)
    const int wn   = wid & 3;        // 0..3 (N)
    const int g    = lane >> 2;      // groupID 0..7
    const int t    = lane & 3;       // threadID_in_group
    const int lrow = lane & 15;
    const int lch  = lane >> 4;

    const int bz = blockIdx.z;
    Ahi += bz * sA; Alo += bz * sA;
    Bhi += bz * sB; Blo += bz * sB;
    if (F32OUT) Cf += bz * sC;
    const int m0 = blockIdx.y * 128;
    const int n0 = blockIdx.x * 128;

    const u32 smem_base = smem_u32(smem);

    float acc[4][4][4];
#pragma unroll
    for (int mi = 0; mi < 4; mi++)
#pragma unroll
        for (int ni = 0; ni < 4; ni++)
#pragma unroll
            for (int c = 0; c < 4; c++) acc[mi][ni][c] = 0.0f;

    const int NC = K >> 5;   // k-chunks of 32

    // precomputed per-thread loader geometry
    const u32 ld_row = (u32)(tid >> 2);        // 0..63 (+64 on second pass)
    const u32 ld_ch  = (u32)(tid & 3);

    // ---- async stage loader: 4 planes (Ahi, Alo, Bhi, Blo), each 128x32 bf16
    auto issue_stage = [&](int c, int buf) {
        const int k0 = c * 32;
        const u32 st = smem_base + buf * STAGE_B;
        const u16* srcs[4] = { Ahi, Alo, Bhi, Blo };
#pragma unroll
        for (int p = 0; p < 4; p++) {
            const u16* src = srcs[p];
            const int rbase = (p < 2) ? m0 : n0;
#pragma unroll
            for (int i = 0; i < 2; i++) {
                const u32 row = ld_row + i * 64;
                cp_async16(st + p * PLANE_B + sw_off(row, ld_ch),
                           src + (long long)(rbase + row) * K + k0 + ld_ch * 8);
            }
        }
        CP_COMMIT();
    };

    issue_stage(0, 0);
    issue_stage(1, 1);

    int buf = 0;          // buffer holding chunk c
    int nbuf = 2;         // buffer that issue_stage(c+2) writes
    for (int c = 0; c < NC; ++c) {
        CP_WAIT1();
        __syncthreads();

        const u32 st = smem_base + buf * STAGE_B;

#pragma unroll
        for (int half = 0; half < 2; half++) {
            const u32 ch = (u32)(half * 2 + lch);

            // ---- B fragments: 2 x ldmatrix.x4 per plane cover all 4 ni ----
            u32 bh[4][2], bl[4][2];
#pragma unroll
            for (int nj = 0; nj < 2; nj++) {
                const u32 rb = sw_off((u32)(wn * 32 + nj * 16 + lrow), ch);
                u32 r0, r1, r2, r3;
                ldmat4(r0, r1, r2, r3, st + 2 * PLANE_B + rb);
                bh[2*nj][0] = r0; bh[2*nj+1][0] = r1;
                bh[2*nj][1] = r2; bh[2*nj+1][1] = r3;
                ldmat4(r0, r1, r2, r3, st + 3 * PLANE_B + rb);
                bl[2*nj][0] = r0; bl[2*nj+1][0] = r1;
                bl[2*nj][1] = r2; bl[2*nj+1][1] = r3;
            }

            // ---- A fragments for an mi-pair, then term-major MMA blocks ----
#pragma unroll
            for (int mp = 0; mp < 2; mp++) {
                u32 ah[2][4], al[2][4];
#pragma unroll
                for (int q = 0; q < 2; q++) {
                    const int mi = mp * 2 + q;
                    const u32 ra = sw_off((u32)(wm * 64 + mi * 16 + lrow), ch);
                    ldmat4(ah[q][0], ah[q][1], ah[q][2], ah[q][3], st + ra);
                    ldmat4(al[q][0], al[q][1], al[q][2], al[q][3], st + PLANE_B + ra);
                }
                // term 1: hi*hi — 8 independent MMAs
#pragma unroll
                for (int q = 0; q < 2; q++)
#pragma unroll
                    for (int ni = 0; ni < 4; ni++)
                        mma_bf16(acc[mp*2+q][ni], ah[q], bh[ni]);
                // term 2: hi*lo
#pragma unroll
                for (int q = 0; q < 2; q++)
#pragma unroll
                    for (int ni = 0; ni < 4; ni++)
                        mma_bf16(acc[mp*2+q][ni], ah[q], bl[ni]);
                // term 3: lo*hi
#pragma unroll
                for (int q = 0; q < 2; q++)
#pragma unroll
                    for (int ni = 0; ni < 4; ni++)
                        mma_bf16(acc[mp*2+q][ni], al[q], bh[ni]);
            }
        }

        // 3-buffer rotation: nbuf was last read at iter c-1; every warp has
        // passed this iter's barrier, so it is safe to overwrite. No second
        // __syncthreads needed.
        if (c + 2 < NC) issue_stage(c + 2, nbuf);
        else            CP_COMMIT();   // keep group accounting uniform

        buf  = (buf  == 2) ? 0 : buf  + 1;
        nbuf = (nbuf == 2) ? 0 : nbuf + 1;
    }

    // ---- epilogue ----
#pragma unroll
    for (int mi = 0; mi < 4; mi++) {
        const int m_lo = m0 + wm * 64 + mi * 16 + g;
        const int m_hi = m_lo + 8;
        const float* pe_lo = posenc ? posenc + (long long)(m_lo & (SEQL - 1)) * N : 0;
        const float* pe_hi = posenc ? posenc + (long long)(m_hi & (SEQL - 1)) * N : 0;
#pragma unroll
        for (int ni = 0; ni < 4; ni++) {
            const int n = n0 + wn * 32 + ni * 8 + 2 * t;
            float2 v0, v1;
            v0.x = acc[mi][ni][0] * alpha;
            v0.y = acc[mi][ni][1] * alpha;
            v1.x = acc[mi][ni][2] * alpha;
            v1.y = acc[mi][ni][3] * alpha;
            if (bias) {
                const float b0 = bias[n], b1 = bias[n + 1];
                v0.x += b0; v0.y += b1;
                v1.x += b0; v1.y += b1;
            }
            if (posenc) {
                v0.x += pe_lo[n]; v0.y += pe_lo[n + 1];
                v1.x += pe_hi[n]; v1.y += pe_hi[n + 1];
            }
            if (F32OUT) {
                *(float2*)(Cf + (long long)m_lo * N + n) = v0;
                *(float2*)(Cf + (long long)m_hi * N + n) = v1;
            }
            if (SPLITOUT) {
                u32 h, l;
                if (!TRANSOUT) {
                    split_pack(v0.x, v0.y, h, l);
                    *(u32*)(Chi + (long long)m_lo * N + n) = h;
                    *(u32*)(Clo + (long long)m_lo * N + n) = l;
                    split_pack(v1.x, v1.y, h, l);
                    *(u32*)(Chi + (long long)m_hi * N + n) = h;
                    *(u32*)(Clo + (long long)m_hi * N + n) = l;
                } else {
                    // V^T: out[b][n][s], m = b*SEQL + s; DMODEL*SEQL = 1<<21
                    const long long base_lo =
                        ((long long)(m_lo >> 11) << 21) + (m_lo & 2047);
                    const long long base_hi =
                        ((long long)(m_hi >> 11) << 21) + (m_hi & 2047);
                    split_pack(v0.x, v0.y, h, l);
                    Chi[base_lo + (long long)n * SEQL]       = (u16)h;
                    Chi[base_lo + (long long)(n + 1) * SEQL] = (u16)(h >> 16);
                    Clo[base_lo + (long long)n * SEQL]       = (u16)l;
                    Clo[base_lo + (long long)(n + 1) * SEQL] = (u16)(l >> 16);
                    split_pack(v1.x, v1.y, h, l);
                    Chi[base_hi + (long long)n * SEQL]       = (u16)h;
                    Chi[base_hi + (long long)(n + 1) * SEQL] = (u16)(h >> 16);
                    Clo[base_hi + (long long)n * SEQL]       = (u16)l;
                    Clo[base_hi + (long long)(n + 1) * SEQL] = (u16)(l >> 16);
                }
            }
        }
    }
}

// ---------------------------------------------------------------------------
// fp32 -> split bf16 hi/lo planes (4 elems per thread)
// ---------------------------------------------------------------------------
__global__ void split_fp32(const float* __restrict__ src,
                           u16* __restrict__ hi, u16* __restrict__ lo, int n4)
{
    const int i = blockIdx.x * blockDim.x + threadIdx.x;
    if (i >= n4) return;
    const float4 v = ((const float4*)src)[i];
    u32 h01, l01, h23, l23;
    split_pack(v.x, v.y, h01, l01);
    split_pack(v.z, v.w, h23, l23);
    ((uint2*)hi)[i] = make_uint2(h01, h23);
    ((uint2*)lo)[i] = make_uint2(l01, l23);
}

// ---------------------------------------------------------------------------
// Row softmax (2048 cols) reading fp32, writing split bf16 planes.
// ---------------------------------------------------------------------------
__global__ void softmax_split(const float* __restrict__ S,
                              u16* __restrict__ hi, u16* __restrict__ lo)
{
    const long long off = (long long)blockIdx.x * 2048;
    const float* row = S + off;
    const int tid = threadIdx.x;
    __shared__ float red[256];

    float v[8];
    *(float4*)&v[0] = *(const float4*)(row + tid * 8);
    *(float4*)&v[4] = *(const float4*)(row + tid * 8 + 4);

    float mx = -1e30f;
#pragma unroll
    for (int i = 0; i < 8; i++) mx = fmaxf(mx, v[i]);
    red[tid] = mx; __syncthreads();
    for (int s = 128; s > 0; s >>= 1) {
        if (tid < s) red[tid] = fmaxf(red[tid], red[tid + s]);
        __syncthreads();
    }
    mx = red[0]; __syncthreads();

    float sum = 0.0f;
#pragma unroll
    for (int i = 0; i < 8; i++) { v[i] = __expf(v[i] - mx); sum += v[i]; }
    red[tid] = sum; __syncthreads();
    for (int s = 128; s > 0; s >>= 1) {
        if (tid < s) red[tid] += red[tid + s];
        __syncthreads();
    }
    const float inv = 1.0f / red[0];

    u32* hp = (u32*)hi + (off >> 1) + tid * 4;
    u32* lp = (u32*)lo + (off >> 1) + tid * 4;
#pragma unroll
    for (int j = 0; j < 4; j++) {
        u32 h, l;
        split_pack(v[2*j] * inv, v[2*j+1] * inv, h, l);
        hp[j] = h; lp[j] = l;
    }
}

// ---------------------------------------------------------------------------
// Plain fp32 row softmax (for the length-2048 pooling weights, 8 rows)
// ---------------------------------------------------------------------------
__global__ void softmax_rows(float* __restrict__ S)
{
    float* row = S + (long long)blockIdx.x * 2048;
    const int tid = threadIdx.x;
    __shared__ float red[256];

    float v[8];
    *(float4*)&v[0] = *(const float4*)(row + tid * 8);
    *(float4*)&v[4] = *(const float4*)(row + tid * 8 + 4);

    float mx = -1e30f;
#pragma unroll
    for (int i = 0; i < 8; i++) mx = fmaxf(mx, v[i]);
    red[tid] = mx; __syncthreads();
    for (int s = 128; s > 0; s >>= 1) {
        if (tid < s) red[tid] = fmaxf(red[tid], red[tid + s]);
        __syncthreads();
    }
    mx = red[0]; __syncthreads();

    float sum = 0.0f;
#pragma unroll
    for (int i = 0; i < 8; i++) { v[i] = __expf(v[i] - mx); sum += v[i]; }
    red[tid] = sum; __syncthreads();
    for (int s = 128; s > 0; s >>= 1) {
        if (tid < s) red[tid] += red[tid + s];
        __syncthreads();
    }
    const float inv = 1.0f / red[0];
#pragma unroll
    for (int i = 0; i < 8; i++) v[i] *= inv;
    *(float4*)(row + tid * 8)     = *(float4*)&v[0];
    *(float4*)(row + tid * 8 + 4) = *(float4*)&v[4];
}

// ---------------------------------------------------------------------------
// h = x + z ; H = LN(h)*g + b  -> fp32 H + split planes
// ---------------------------------------------------------------------------
__global__ void add_ln_split(const float* __restrict__ X, const float* __restrict__ Z,
                             const float* __restrict__ g, const float* __restrict__ b,
                             float* __restrict__ H, u16* __restrict__ hi, u16* __restrict__ lo)
{
    const long long r = blockIdx.x;
    const int tid = threadIdx.x;
    const int c0  = tid * 4;
    const float* xr = X + r * DMODEL;
    const float* zr = Z + r * DMODEL;
    __shared__ float red[256];

    float4 x4 = *(const float4*)(xr + c0);
    float4 z4 = *(const float4*)(zr + c0);
    float h[4] = { x4.x + z4.x, x4.y + z4.y, x4.z + z4.z, x4.w + z4.w };

    float sum = h[0] + h[1] + h[2] + h[3];
    red[tid] = sum; __syncthreads();
    for (int s = 128; s > 0; s >>= 1) {
        if (tid < s) red[tid] += red[tid + s];
        __syncthreads();
    }
    const float mean = red[0] * (1.0f / DMODEL);
    __syncthreads();

    float vs = 0.0f;
#pragma unroll
    for (int i = 0; i < 4; i++) { const float d = h[i] - mean; vs += d * d; }
    red[tid] = vs; __syncthreads();
    for (int s = 128; s > 0; s >>= 1) {
        if (tid < s) red[tid] += red[tid + s];
        __syncthreads();
    }
    const float inv = rsqrtf(red[0] * (1.0f / DMODEL) + LN_EPS);

    float4 o;
    o.x = (h[0] - mean) * inv * g[c0 + 0] + b[c0 + 0];
    o.y = (h[1] - mean) * inv * g[c0 + 1] + b[c0 + 1];
    o.z = (h[2] - mean) * inv * g[c0 + 2] + b[c0 + 2];
    o.w = (h[3] - mean) * inv * g[c0 + 3] + b[c0 + 3];
    *(float4*)(H + r * DMODEL + c0) = o;

    u32 h01, l01, h23, l23;
    split_pack(o.x, o.y, h01, l01);
    split_pack(o.z, o.w, h23, l23);
    const long long pi = (r * DMODEL + c0) >> 1;
    ((u32*)hi)[pi]     = h01;
    ((u32*)hi)[pi + 1] = h23;
    ((u32*)lo)[pi]     = l01;
    ((u32*)lo)[pi + 1] = l23;
}

// ---------------------------------------------------------------------------
// t[r] = sum_o tanh(SK[r,o]) * q[o]
// ---------------------------------------------------------------------------
__global__ void softkey_reduce(const float* __restrict__ SK, const float* __restrict__ q,
                               float* __restrict__ t)
{
    const long long r = blockIdx.x;
    const int tid = threadIdx.x;
    __shared__ float red[256];

    float s = 0.0f;
#pragma unroll
    for (int i = 0; i < 4; i++) {
        const int c = tid + i * 256;
        s += tanhf(SK[r * DMODEL + c]) * q[c];
    }
    red[tid] = s; __syncthreads();
    for (int k = 128; k > 0; k >>= 1) {
        if (tid < k) red[tid] += red[tid + k];
        __syncthreads();
    }
    if (tid == 0) t[r] = red[0];
}

// ---------------------------------------------------------------------------
// out[b,o] = sum_s w[b,s] * H[b,s,o]
// ---------------------------------------------------------------------------
__global__ void final_out(const float* __restrict__ H, const float* __restrict__ w,
                          float* __restrict__ out)
{
    const int b = blockIdx.y;
    const int o = blockIdx.x * 256 + threadIdx.x;
    const float* Hb = H + (long long)b * SEQL * DMODEL;
    const float* wb = w + (long long)b * SEQL;

    float a0 = 0.0f, a1 = 0.0f, a2 = 0.0f, a3 = 0.0f;
    for (int s = 0; s < SEQL; s += 4) {
        a0 += wb[s + 0] * Hb[(long long)(s + 0) * DMODEL + o];
        a1 += wb[s + 1] * Hb[(long long)(s + 1) * DMODEL + o];
        a2 += wb[s + 2] * Hb[(long long)(s + 2) * DMODEL + o];
        a3 += wb[s + 3] * Hb[(long long)(s + 3) * DMODEL + o];
    }
    out[b * DMODEL + o] = (a0 + a1) + (a2 + a3);
}

// ---------------------------------------------------------------------------
// Launch
// ---------------------------------------------------------------------------
extern "C" void kernel_launch(void* const* d_in, const int* in_sizes, int n_in,
                              void* d_out, int out_size)
{
    const float* inputs  = (const float*)d_in[0];
    const float* embed_w = (const float*)d_in[1];
    const float* embed_b = (const float*)d_in[2];
    const float* wq_w    = (const float*)d_in[3];
    const float* wq_b    = (const float*)d_in[4];
    const float* wk_w    = (const float*)d_in[5];
    const float* wk_b    = (const float*)d_in[6];
    const float* wv_w    = (const float*)d_in[7];
    const float* wv_b    = (const float*)d_in[8];
    const float* ln_g    = (const float*)d_in[9];
    const float* ln_b    = (const float*)d_in[10];
    const float* skw     = (const float*)d_in[11];
    const float* sq      = (const float*)d_in[12];
    const float* pos     = (const float*)d_in[13];
    float* out = (float*)d_out;

    cudaFuncSetAttribute((const void*)tc_gemm<true,  true,  false>,
                         cudaFuncAttributeMaxDynamicSharedMemorySize, DYN_SMEM_G);
    cudaFuncSetAttribute((const void*)tc_gemm<false, true,  false>,
                         cudaFuncAttributeMaxDynamicSharedMemorySize, DYN_SMEM_G);
    cudaFuncSetAttribute((const void*)tc_gemm<false, true,  true>,
                         cudaFuncAttributeMaxDynamicSharedMemorySize, DYN_SMEM_G);
    cudaFuncSetAttribute((const void*)tc_gemm<true,  false, false>,
                         cudaFuncAttributeMaxDynamicSharedMemorySize, DYN_SMEM_G);

    float* base = 0;
    cudaGetSymbolAddress((void**)&base, g_scratch);

    u16* INh  = (u16*)(base + O_INS);   u16* INl  = INh  + C_IN;
    u16* EWh  = (u16*)(base + O_EWS);   u16* EWl  = EWh  + C_EW;
    u16* WQh  = (u16*)(base + O_WQS);   u16* WQl  = WQh  + C_W;
    u16* WKh  = (u16*)(base + O_WKS);   u16* WKl  = WKh  + C_W;
    u16* WVh  = (u16*)(base + O_WVS);   u16* WVl  = WVh  + C_W;
    u16* SKWh = (u16*)(base + O_SKWS);  u16* SKWl = SKWh + C_W;
    float* X  = base + O_X;
    u16* Xh   = (u16*)(base + O_XS);    u16* Xl   = Xh   + C_MAT;
    u16* Qh   = (u16*)(base + O_QS);    u16* Ql   = Qh   + C_MAT;
    u16* Kh   = (u16*)(base + O_KS);    u16* Kl   = Kh   + C_MAT;
    u16* VTh  = (u16*)(base + O_VTS);   u16* VTl  = VTh  + C_MAT;
    float* SC = base + O_SC;
    u16* SCh  = (u16*)(base + O_SCS);   u16* SCl  = SCh  + C_SC;
    float* Z  = base + O_Z;
    float* H  = base + O_H;
    u16* Hh   = (u16*)(base + O_HS);    u16* Hl   = Hh   + C_MAT;
    float* SK = base + O_SK;
    float* T  = base + O_T;

    // 0) one-time splits of raw inputs & weights
    split_fp32<<<(int)(C_IN / 4 / 256), 256>>>(inputs,  INh,  INl,  (int)(C_IN / 4));
    split_fp32<<<(int)(C_EW / 4 / 256), 256>>>(embed_w, EWh,  EWl,  (int)(C_EW / 4));
    split_fp32<<<(int)(C_W  / 4 / 256), 256>>>(wq_w,    WQh,  WQl,  (int)(C_W  / 4));
    split_fp32<<<(int)(C_W  / 4 / 256), 256>>>(wk_w,    WKh,  WKl,  (int)(C_W  / 4));
    split_fp32<<<(int)(C_W  / 4 / 256), 256>>>(wv_w,    WVh,  WVl,  (int)(C_W  / 4));
    split_fp32<<<(int)(C_W  / 4 / 256), 256>>>(skw,     SKWh, SKWl, (int)(C_W  / 4));

    // 1) embed: X = inputs @ embed_w^T + embed_b + pos_enc  (fp32 + split out)
    tc_gemm<true, true, false><<<dim3(DMODEL / 128, NROW / 128, 1), 256, DYN_SMEM_G>>>(
        INh, INl, EWh, EWl, X, Xh, Xl,
        NROW, DMODEL, D_IN, 0, 0, 0, 1.0f, embed_b, pos);

    // 2) Q, K (split out), V (transposed split out)
    tc_gemm<false, true, false><<<dim3(DMODEL / 128, NROW / 128, 1), 256, DYN_SMEM_G>>>(
        Xh, Xl, WQh, WQl, 0, Qh, Ql,
        NROW, DMODEL, DMODEL, 0, 0, 0, 1.0f, wq_b, 0);
    tc_gemm<false, true, false><<<dim3(DMODEL / 128, NROW / 128, 1), 256, DYN_SMEM_G>>>(
        Xh, Xl, WKh, WKl, 0, Kh, Kl,
        NROW, DMODEL, DMODEL, 0, 0, 0, 1.0f, wk_b, 0);
    tc_gemm<false, true, true><<<dim3(DMODEL / 128, NROW / 128, 1), 256, DYN_SMEM_G>>>(
        Xh, Xl, WVh, WVl, 0, VTh, VTl,
        NROW, DMODEL, DMODEL, 0, 0, 0, 1.0f, wv_b, 0);

    // 3) scores = Q @ K^T / 32 (batched, fp32 out)
    tc_gemm<true, false, false><<<dim3(SEQL / 128, SEQL / 128, BATCH), 256, DYN_SMEM_G>>>(
        Qh, Ql, Kh, Kl, SC, 0, 0,
        SEQL, SEQL, DMODEL,
        (long long)SEQL * DMODEL, (long long)SEQL * DMODEL, (long long)SEQL * SEQL,
        1.0f / 32.0f, 0, 0);

    // 4) softmax -> split planes
    softmax_split<<<NROW, 256>>>(SC, SCh, SCl);

    // 5) Z = softmax(SC) @ V  (B = V^T planes, [n][k] per batch)
    tc_gemm<true, false, false><<<dim3(DMODEL / 128, SEQL / 128, BATCH), 256, DYN_SMEM_G>>>(
        SCh, SCl, VTh, VTl, Z, 0, 0,
        SEQL, DMODEL, SEQL,
        (long long)SEQL * SEQL, (long long)DMODEL * SEQL, (long long)SEQL * DMODEL,
        1.0f, 0, 0);

    // 6) H = LN(X + Z)*g + b  (fp32 + split)
    add_ln_split<<<NROW, 256>>>(X, Z, ln_g, ln_b, H, Hh, Hl);

    // 7) SK = H @ soft_key_w^T (fp32 out)
    tc_gemm<true, false, false><<<dim3(DMODEL / 128, NROW / 128, 1), 256, DYN_SMEM_G>>>(
        Hh, Hl, SKWh, SKWl, SK, 0, 0,
        NROW, DMODEL, DMODEL, 0, 0, 0, 1.0f, 0, 0);

    // 8) t[b,s] = sum_o tanh(SK)*soft_query[o]; softmax over s per batch
    softkey_reduce<<<NROW, 256>>>(SK, sq, T);
    softmax_rows<<<BATCH, 256>>>(T);

    // 9) out[b,o] = sum_s w[b,s] * H[b,s,o]
    final_out<<<dim3(DMODEL / 256, BATCH), 256>>>(H, T, out);
}